// round 13
// baseline (speedup 1.0000x reference)
#include <cuda_runtime.h>
#include <math.h>

#define Nn   4
#define MA   256
#define NFS  128
#define KK   8
#define HID  256
#define OUTD 32
#define RCf  5.0f
#define PIf  3.14159265358979323846f
#define ROWS (Nn*MA)   // 1024

#define FMA_F32X2(d, a, b, c) \
    asm("fma.rn.f32x2 %0, %1, %2, %3;" : "=l"(d) : "l"(a), "l"(b), "l"(c))
#define PACK2(d, x) \
    asm("mov.b64 %0, {%1, %1};" : "=l"(d) : "r"(__float_as_uint(x)))
#define UNPACK2(lo, hi, v) \
    asm("mov.b64 {%0, %1}, %2;" : "=r"(lo), "=r"(hi) : "l"(v))

// ---------------- scratch ---------------------------------------------------
__device__ float g_a[ROWS];
__device__ float g_b[ROWS];
__device__ float g_p[ROWS*HID];
__device__ float g_q[ROWS*HID];

// grid barrier state (generation/sense-reversal; safe across graph replays)
__device__ unsigned int g_bar_count = 0;
__device__ unsigned int g_bar_gen   = 0;

__device__ __forceinline__ void grid_barrier(int nblocks) {
    __threadfence();
    __syncthreads();
    if (threadIdx.x == 0) {
        const unsigned int gen = *(volatile unsigned int*)&g_bar_gen;
        const unsigned int tk  = atomicAdd(&g_bar_count, 1u);
        if (tk == (unsigned)nblocks - 1u) {
            g_bar_count = 0u;
            __threadfence();
            atomicAdd(&g_bar_gen, 1u);
        } else {
            while (*(volatile unsigned int*)&g_bar_gen == gen) __nanosleep(64);
        }
        __threadfence();
    }
    __syncthreads();
}

// shared memory: phase-1 and phase-2 layouts overlap (separated by barrier)
union __align__(16) Smem {
    struct { float hsT[NFS][8]; } p1;                 // 4KB
    struct {
        float px[MA], py[MA], pz[MA];
        unsigned long long scand[64];
        float wsum[8];
        float satt[KK]; int sidx[KK];
        float sdx[KK], sdy[KK], sdz[KK];
        float hidT[HID][KK];                          // 8KB
        float sp[8*256];                              // 8KB
    } p2;
};

// ---------------- fused kernel: projections -> barrier -> attention/MLP ----
__global__ void __launch_bounds__(256, 7) kFused(
        const int*   __restrict__ z,
        const float* __restrict__ r,
        const float* __restrict__ h,
        const float* __restrict__ Wa,
        const float* __restrict__ ba_,
        const float* __restrict__ Wp1,
        const float* __restrict__ bp1,
        const float* __restrict__ Wp2,
        const float* __restrict__ bp2,
        float* __restrict__ out, int has_prefix,
        float* __restrict__ cout, int nblocks) {
    __shared__ Smem smem;
    const int t = threadIdx.x;

    // ===== phase 1: p/q/a/b projections (512 units: 8 rows x 64-col quarter)
    if (blockIdx.x < 512) {
        const int row0 = (blockIdx.x >> 2) * 8;       // 128 row-chunks
        const int colq = blockIdx.x & 3;              // 4 col-quarters

        if (t < NFS) {   // transpose-load h: thread t = feature t, 8 rows
            float v[8];
#pragma unroll
            for (int rr = 0; rr < 8; rr++) v[rr] = h[(size_t)(row0+rr)*NFS + t];
#pragma unroll
            for (int rr = 0; rr < 8; rr++) smem.p1.hsT[t][rr] = v[rr];
        }
        if (has_prefix && blockIdx.x < 16) {
            const int gt = blockIdx.x * 256 + t;       // 0..4095
            if (gt < ROWS)   out[gt] = (float)z[gt];
            if (gt < ROWS*3) out[ROWS + gt] = r[gt];
        }
        __syncthreads();

        const int col = colq*64 + (t & 63);
        const int grp = (t >> 6) & 1;                  // 0 -> p, 1 -> q
        const int rh  = t >> 7;                        // rows rh*4 .. rh*4+3
        const float* wbase = Wp1 + (size_t)(grp*NFS)*HID + col;

        unsigned long long acc0 = 0ULL, acc1 = 0ULL;   // row pairs within quad
#pragma unroll 8
        for (int f = 0; f < NFS; f++) {
            const float w = __ldg(wbase + (size_t)f*HID);
            unsigned long long ww; PACK2(ww, w);
            const ulonglong2 hv = *(const ulonglong2*)&smem.p1.hsT[f][rh*4];
            FMA_F32X2(acc0, hv.x, ww, acc0);
            FMA_F32X2(acc1, hv.y, ww, acc1);
        }
        float* gdst = grp ? g_q : g_p;
        {
            unsigned int lo, hi;
            UNPACK2(lo, hi, acc0);
            gdst[(size_t)(row0 + rh*4 + 0)*HID + col] = __uint_as_float(lo);
            gdst[(size_t)(row0 + rh*4 + 1)*HID + col] = __uint_as_float(hi);
            UNPACK2(lo, hi, acc1);
            gdst[(size_t)(row0 + rh*4 + 2)*HID + col] = __uint_as_float(lo);
            gdst[(size_t)(row0 + rh*4 + 3)*HID + col] = __uint_as_float(hi);
        }

        // a,b dots: only colq==0 blocks; warp w handles row w
        if (colq == 0) {
            const int w = t >> 5, lane = t & 31;
            float sa = 0.f, sb_ = 0.f;
#pragma unroll
            for (int f4 = 0; f4 < NFS/32; f4++) {
                const int f = f4*32 + lane;
                const float hv = smem.p1.hsT[f][w];
                sa  = fmaf(hv, Wa[f],     sa);
                sb_ = fmaf(hv, Wa[NFS+f], sb_);
            }
#pragma unroll
            for (int off = 16; off; off >>= 1) {
                sa  += __shfl_down_sync(0xffffffffu, sa,  off);
                sb_ += __shfl_down_sync(0xffffffffu, sb_, off);
            }
            if (lane == 0) { g_a[row0+w] = sa; g_b[row0+w] = sb_; }
        }
    }

    // ================= grid-wide barrier ===================================
    grid_barrier(nblocks);

    // ================= phase 2: attention + topK + MLP + output ============
    const float b1 = bp1[t];

    for (int row = blockIdx.x; row < ROWS; row += gridDim.x) {
        const int n   = row >> 8;
        const int i   = row & (MA-1);
        const int bse = n * MA;
        const int j   = t;

        const float pv = g_p[(size_t)row*HID + t];   // early prefetch

        const float rjx = r[(size_t)(bse+j)*3 + 0];
        const float rjy = r[(size_t)(bse+j)*3 + 1];
        const float rjz = r[(size_t)(bse+j)*3 + 2];
        const float rix = __ldg(&r[(size_t)(bse+i)*3 + 0]);
        const float riy = __ldg(&r[(size_t)(bse+i)*3 + 1]);
        const float riz = __ldg(&r[(size_t)(bse+i)*3 + 2]);
        const int   zj  = z[bse+j];
        const int   zi  = __ldg(&z[bse+i]);
        const float bj  = g_b[bse+j];
        const float av  = __ldg(&g_a[row]);
        const float bav = __ldg(&ba_[0]);
        smem.p2.px[j] = rjx; smem.p2.py[j] = rjy; smem.p2.pz[j] = rjz;

        // ---- attention score ----
        const float dx = rjx-rix, dy = rjy-riy, dz = rjz-riz;
        const float d  = sqrtf(dx*dx + dy*dy + dz*dz);
        const bool  msk = (zi > -1) && (zj > -1) && (j != i);
        float g = 0.f;
        if (msk) {
            const float cf = 0.5f * (__cosf(fminf(d, RCf) * (PIf/RCf)) + 1.f);
            g = __expf(av + cf*bj + bav);
        }

        // ---- warp sums of g ----
        float s = g;
#pragma unroll
        for (int off = 16; off; off >>= 1) s += __shfl_xor_sync(0xffffffffu, s, off);
        if ((t & 31) == 0) smem.p2.wsum[t >> 5] = s;

        // ---- intra-warp exact full rank on unique u64 keys ----
        const unsigned long long key =
            (((unsigned long long)__float_as_uint(g)) << 32) | (unsigned)(MA-1-j);
        int rk = 0;
#pragma unroll
        for (int sft = 1; sft < 32; sft++) {
            const unsigned long long ok = __shfl_xor_sync(0xffffffffu, key, sft);
            rk += (ok > key);
        }
        if (rk < KK) smem.p2.scand[(t >> 5)*KK + rk] = key;
        __syncthreads();

        // ---- warp 0: rank the 64 candidates, emit global top-8 ----
        if (t < 32) {
            float sumg = 0.f;
#pragma unroll
            for (int w = 0; w < 8; w++) sumg += smem.p2.wsum[w];
            const float invsum = __fdividef(1.f, fmaxf(sumg, 1e-8f));

            const unsigned long long k0 = smem.p2.scand[t];
            const unsigned long long k1 = smem.p2.scand[t + 32];
            int r0 = 0, r1 = 0;
#pragma unroll 8
            for (int m = 0; m < 64; m++) {
                const unsigned long long km = smem.p2.scand[m];
                r0 += (km > k0);
                r1 += (km > k1);
            }
#pragma unroll
            for (int pick = 0; pick < 2; pick++) {
                const unsigned long long kk = pick ? k1 : k0;
                const int rr = pick ? r1 : r0;
                if (rr < KK) {
                    const int jw = MA - 1 - (int)(kk & 0xffffffffu);
                    smem.p2.satt[rr] = __uint_as_float((unsigned)(kk >> 32)) * invsum;
                    smem.p2.sidx[rr] = jw;
                    const float ddx = smem.p2.px[jw]-rix;
                    const float ddy = smem.p2.py[jw]-riy;
                    const float ddz = smem.p2.pz[jw]-riz;
                    const float dd  = sqrtf(ddx*ddx + ddy*ddy + ddz*ddz);
                    const float inv = __fdividef(1.f, fmaxf(dd, 1e-4f));
                    smem.p2.sdx[rr] = ddx*inv;
                    smem.p2.sdy[rr] = ddy*inv;
                    smem.p2.sdz[rr] = ddz*inv;
                }
            }
        }
        __syncthreads();

        // ---- MLP layer 1 -> hidT[t][k] (k contiguous) ----
        {
            float xv[KK];
#pragma unroll
            for (int k = 0; k < KK; k++) {
                const float x = fmaf(smem.p2.satt[k],
                        pv + g_q[(size_t)(bse + smem.p2.sidx[k])*HID + t], b1);
                xv[k] = __fdividef(x, 1.f + __expf(-x));   // silu
            }
            float4* dst = (float4*)&smem.p2.hidT[t][0];
            dst[0] = make_float4(xv[0], xv[1], xv[2], xv[3]);
            dst[1] = make_float4(xv[4], xv[5], xv[6], xv[7]);
        }
        __syncthreads();

        // ---- layer 2 matvec via f32x2: thread = (o, tt-range of 32) ----
        {
            const int o  = t & 31;
            const int tg = t >> 5;
            unsigned long long a01 = 0ULL, a23 = 0ULL, a45 = 0ULL, a67 = 0ULL;
#pragma unroll 8
            for (int u = 0; u < 32; u++) {
                const int tt = tg*32 + u;
                const float w = __ldg(&Wp2[(size_t)tt*OUTD + o]);
                unsigned long long ww; PACK2(ww, w);
                const ulonglong2 hA = *(const ulonglong2*)&smem.p2.hidT[tt][0];
                const ulonglong2 hB = *(const ulonglong2*)&smem.p2.hidT[tt][4];
                FMA_F32X2(a01, hA.x, ww, a01);
                FMA_F32X2(a23, hA.y, ww, a23);
                FMA_F32X2(a45, hB.x, ww, a45);
                FMA_F32X2(a67, hB.y, ww, a67);
            }
            unsigned int l0,h0,l1,h1,l2,h2,l3,h3;
            UNPACK2(l0, h0, a01); UNPACK2(l1, h1, a23);
            UNPACK2(l2, h2, a45); UNPACK2(l3, h3, a67);
            smem.p2.sp[tg*256 + 0*32 + o] = __uint_as_float(l0);
            smem.p2.sp[tg*256 + 1*32 + o] = __uint_as_float(h0);
            smem.p2.sp[tg*256 + 2*32 + o] = __uint_as_float(l1);
            smem.p2.sp[tg*256 + 3*32 + o] = __uint_as_float(h1);
            smem.p2.sp[tg*256 + 4*32 + o] = __uint_as_float(l2);
            smem.p2.sp[tg*256 + 5*32 + o] = __uint_as_float(h2);
            smem.p2.sp[tg*256 + 6*32 + o] = __uint_as_float(l3);
            smem.p2.sp[tg*256 + 7*32 + o] = __uint_as_float(h3);
        }
        __syncthreads();

        // ---- finalize: combine 8 partials, bias + direction, store ----
        {
            const int k = t >> 5;
            const int o = t & 31;
            float acc = bp2[o];
#pragma unroll
            for (int tg = 0; tg < 8; tg++) acc += smem.p2.sp[tg*256 + t];
            const size_t ob = ((size_t)(row*KK + k)*OUTD + o) * 3;
            cout[ob+0] = acc * smem.p2.sdx[k];
            cout[ob+1] = acc * smem.p2.sdy[k];
            cout[ob+2] = acc * smem.p2.sdz[k];
        }
    }
}

// ---------------------------------------------------------------------------
extern "C" void kernel_launch(void* const* d_in, const int* in_sizes, int n_in,
                              void* d_out, int out_size) {
    const int*   z   = (const int*)  d_in[0];
    const float* r   = (const float*)d_in[1];
    const float* h   = (const float*)d_in[2];
    const float* Wa  = (const float*)d_in[3];
    const float* ba  = (const float*)d_in[4];
    const float* Wp1 = (const float*)d_in[5];
    const float* bp1 = (const float*)d_in[6];
    const float* Wp2 = (const float*)d_in[7];
    const float* bp2 = (const float*)d_in[8];

    float* out = (float*)d_out;
    const int CSZ  = Nn*MA*KK*OUTD*3;         // 786432
    const int PREF = ROWS + ROWS*3;           // 4096 (z + r)
    const int has_prefix = (out_size == CSZ + PREF) ? 1 : 0;
    float* cout = has_prefix ? (out + PREF) : out;

    int dev = 0;
    cudaGetDevice(&dev);
    int sms = 148;
    cudaDeviceGetAttribute(&sms, cudaDevAttrMultiProcessorCount, dev);
    int blocks = sms * 7;                      // all co-resident (LB(256,7))
    if (blocks > ROWS) blocks = ROWS;          // 1024 rows max useful
    if (blocks < 512)  blocks = 512;           // phase-1 needs 512 blocks

    kFused<<<blocks, 256>>>(z, r, h, Wa, ba, Wp1, bp1, Wp2, bp2,
                            out, has_prefix, cout, blocks);
}

// round 14
// speedup vs baseline: 1.0300x; 1.0300x over previous
#include <cuda_runtime.h>
#include <math.h>

#define Nn   4
#define MA   256
#define NFS  128
#define KK   8
#define HID  256
#define OUTD 32
#define RCf  5.0f
#define PIf  3.14159265358979323846f
#define ROWS (Nn*MA)   // 1024
#define HP   20        // hsT row stride in floats (16B-aligned, conflict-reduced)

#define FMA_F32X2(d, a, b, c) \
    asm("fma.rn.f32x2 %0, %1, %2, %3;" : "=l"(d) : "l"(a), "l"(b), "l"(c))
#define PACK2(d, x) \
    asm("mov.b64 %0, {%1, %1};" : "=l"(d) : "r"(__float_as_uint(x)))
#define UNPACK2(lo, hi, v) \
    asm("mov.b64 {%0, %1}, %2;" : "=r"(lo), "=r"(hi) : "l"(v))

// ---------------- scratch ---------------------------------------------------
__device__ float g_a[ROWS];
__device__ float g_b[ROWS];
__device__ float g_p[ROWS*HID];
__device__ float g_q[ROWS*HID];

// grid barrier state (generation/sense-reversal; safe across graph replays)
__device__ unsigned int g_bar_count = 0;
__device__ unsigned int g_bar_gen   = 0;

__device__ __forceinline__ void grid_barrier(int nblocks) {
    __threadfence();
    __syncthreads();
    if (threadIdx.x == 0) {
        const unsigned int gen = *(volatile unsigned int*)&g_bar_gen;
        const unsigned int tk  = atomicAdd(&g_bar_count, 1u);
        if (tk == (unsigned)nblocks - 1u) {
            g_bar_count = 0u;
            __threadfence();
            atomicAdd(&g_bar_gen, 1u);
        } else {
            while (*(volatile unsigned int*)&g_bar_gen == gen) __nanosleep(64);
        }
        __threadfence();
    }
    __syncthreads();
}

// shared memory: phase-1 and phase-2 layouts overlap (separated by barrier)
union __align__(16) Smem {
    struct { float hsT[NFS][HP]; } p1;                // 10KB ([f][row0..15,pad])
    struct {
        float px[MA], py[MA], pz[MA];
        unsigned long long scand[64];
        float wsum[8];
        float satt[KK]; int sidx[KK];
        float sdx[KK], sdy[KK], sdz[KK];
        float hidT[HID][KK];                          // 8KB
        float sp[8*256];                              // 8KB
    } p2;
};

// ---------------- fused kernel: projections -> barrier -> attention/MLP ----
__global__ void __launch_bounds__(256, 7) kFused(
        const int*   __restrict__ z,
        const float* __restrict__ r,
        const float* __restrict__ h,
        const float* __restrict__ Wa,
        const float* __restrict__ ba_,
        const float* __restrict__ Wp1,
        const float* __restrict__ bp1,
        const float* __restrict__ Wp2,
        const float* __restrict__ bp2,
        float* __restrict__ out, int has_prefix,
        float* __restrict__ cout, int nblocks) {
    __shared__ Smem smem;
    const int t = threadIdx.x;

    // ===== phase 1: 512 units = 64 row-chunks (16 rows) x 8 col-groups (32)
    if (blockIdx.x < 512) {
        const int row0 = (blockIdx.x >> 3) * 16;      // 64 row-chunks
        const int cg   = blockIdx.x & 7;              // 8 col-groups

        if (t < NFS) {   // transpose-load h: thread t = feature t, 16 rows
            float v[16];
#pragma unroll
            for (int rr = 0; rr < 16; rr++) v[rr] = h[(size_t)(row0+rr)*NFS + t];
#pragma unroll
            for (int rr = 0; rr < 16; rr++) smem.p1.hsT[t][rr] = v[rr];
        }
        if (has_prefix && blockIdx.x < 16) {
            const int gt = blockIdx.x * 256 + t;       // 0..4095
            if (gt < ROWS)   out[gt] = (float)z[gt];
            if (gt < ROWS*3) out[ROWS + gt] = r[gt];
        }
        __syncthreads();

        const int col = cg*32 + (t & 31);
        const int grp = (t >> 5) & 1;                  // 0 -> p, 1 -> q
        const int rq  = t >> 6;                        // rows rq*4 .. rq*4+3
        const float* wbase = Wp1 + (size_t)(grp*NFS)*HID + col;

        unsigned long long acc0 = 0ULL, acc1 = 0ULL;   // 4 rows (2 pairs)
#pragma unroll 8
        for (int f = 0; f < NFS; f++) {
            const float w = __ldg(wbase + (size_t)f*HID);
            unsigned long long ww; PACK2(ww, w);
            const ulonglong2 hv = *(const ulonglong2*)&smem.p1.hsT[f][rq*4];
            FMA_F32X2(acc0, hv.x, ww, acc0);
            FMA_F32X2(acc1, hv.y, ww, acc1);
        }
        float* gdst = grp ? g_q : g_p;
        {
            unsigned int lo, hi;
            UNPACK2(lo, hi, acc0);
            gdst[(size_t)(row0 + rq*4 + 0)*HID + col] = __uint_as_float(lo);
            gdst[(size_t)(row0 + rq*4 + 1)*HID + col] = __uint_as_float(hi);
            UNPACK2(lo, hi, acc1);
            gdst[(size_t)(row0 + rq*4 + 2)*HID + col] = __uint_as_float(lo);
            gdst[(size_t)(row0 + rq*4 + 3)*HID + col] = __uint_as_float(hi);
        }

        // a,b dots: only cg==0 blocks; warp w handles rows 2w, 2w+1
        if (cg == 0) {
            const int w = t >> 5, lane = t & 31;
            float sa0 = 0.f, sb0 = 0.f, sa1 = 0.f, sb1 = 0.f;
#pragma unroll
            for (int f4 = 0; f4 < NFS/32; f4++) {
                const int f = f4*32 + lane;
                const float wa0 = Wa[f], wa1 = Wa[NFS+f];
                const float h0 = smem.p1.hsT[f][2*w];
                const float h1 = smem.p1.hsT[f][2*w+1];
                sa0 = fmaf(h0, wa0, sa0); sb0 = fmaf(h0, wa1, sb0);
                sa1 = fmaf(h1, wa0, sa1); sb1 = fmaf(h1, wa1, sb1);
            }
#pragma unroll
            for (int off = 16; off; off >>= 1) {
                sa0 += __shfl_down_sync(0xffffffffu, sa0, off);
                sb0 += __shfl_down_sync(0xffffffffu, sb0, off);
                sa1 += __shfl_down_sync(0xffffffffu, sa1, off);
                sb1 += __shfl_down_sync(0xffffffffu, sb1, off);
            }
            if (lane == 0) {
                g_a[row0 + 2*w]     = sa0; g_b[row0 + 2*w]     = sb0;
                g_a[row0 + 2*w + 1] = sa1; g_b[row0 + 2*w + 1] = sb1;
            }
        }
    }

    // ================= grid-wide barrier ===================================
    grid_barrier(nblocks);

    // ================= phase 2: attention + topK + MLP + output ============
    const float b1 = bp1[t];

    for (int row = blockIdx.x; row < ROWS; row += gridDim.x) {
        const int n   = row >> 8;
        const int i   = row & (MA-1);
        const int bse = n * MA;
        const int j   = t;

        const float pv = g_p[(size_t)row*HID + t];   // early prefetch

        const float rjx = r[(size_t)(bse+j)*3 + 0];
        const float rjy = r[(size_t)(bse+j)*3 + 1];
        const float rjz = r[(size_t)(bse+j)*3 + 2];
        const float rix = __ldg(&r[(size_t)(bse+i)*3 + 0]);
        const float riy = __ldg(&r[(size_t)(bse+i)*3 + 1]);
        const float riz = __ldg(&r[(size_t)(bse+i)*3 + 2]);
        const int   zj  = z[bse+j];
        const int   zi  = __ldg(&z[bse+i]);
        const float bj  = g_b[bse+j];
        const float av  = __ldg(&g_a[row]);
        const float bav = __ldg(&ba_[0]);
        smem.p2.px[j] = rjx; smem.p2.py[j] = rjy; smem.p2.pz[j] = rjz;

        // ---- attention score ----
        const float dx = rjx-rix, dy = rjy-riy, dz = rjz-riz;
        const float d  = sqrtf(dx*dx + dy*dy + dz*dz);
        const bool  msk = (zi > -1) && (zj > -1) && (j != i);
        float g = 0.f;
        if (msk) {
            const float cf = 0.5f * (__cosf(fminf(d, RCf) * (PIf/RCf)) + 1.f);
            g = __expf(av + cf*bj + bav);
        }

        // ---- warp sums of g ----
        float s = g;
#pragma unroll
        for (int off = 16; off; off >>= 1) s += __shfl_xor_sync(0xffffffffu, s, off);
        if ((t & 31) == 0) smem.p2.wsum[t >> 5] = s;

        // ---- intra-warp exact full rank on unique u64 keys ----
        const unsigned long long key =
            (((unsigned long long)__float_as_uint(g)) << 32) | (unsigned)(MA-1-j);
        int rk = 0;
#pragma unroll
        for (int sft = 1; sft < 32; sft++) {
            const unsigned long long ok = __shfl_xor_sync(0xffffffffu, key, sft);
            rk += (ok > key);
        }
        if (rk < KK) smem.p2.scand[(t >> 5)*KK + rk] = key;
        __syncthreads();

        // ---- threads 0..63: each ranks ONE candidate, emit global top-8 ----
        if (t < 64) {
            float sumg = 0.f;
#pragma unroll
            for (int w = 0; w < 8; w++) sumg += smem.p2.wsum[w];
            const float invsum = __fdividef(1.f, fmaxf(sumg, 1e-8f));

            const unsigned long long k0 = smem.p2.scand[t];
            int r0 = 0;
#pragma unroll 16
            for (int m = 0; m < 64; m++)
                r0 += (smem.p2.scand[m] > k0);

            if (r0 < KK) {
                const int jw = MA - 1 - (int)(k0 & 0xffffffffu);
                smem.p2.satt[r0] = __uint_as_float((unsigned)(k0 >> 32)) * invsum;
                smem.p2.sidx[r0] = jw;
                const float ddx = smem.p2.px[jw]-rix;
                const float ddy = smem.p2.py[jw]-riy;
                const float ddz = smem.p2.pz[jw]-riz;
                const float dd  = sqrtf(ddx*ddx + ddy*ddy + ddz*ddz);
                const float inv = __fdividef(1.f, fmaxf(dd, 1e-4f));
                smem.p2.sdx[r0] = ddx*inv;
                smem.p2.sdy[r0] = ddy*inv;
                smem.p2.sdz[r0] = ddz*inv;
            }
        }
        __syncthreads();

        // ---- MLP layer 1 -> hidT[t][k] (k contiguous) ----
        {
            float xv[KK];
#pragma unroll
            for (int k = 0; k < KK; k++) {
                const float x = fmaf(smem.p2.satt[k],
                        pv + g_q[(size_t)(bse + smem.p2.sidx[k])*HID + t], b1);
                xv[k] = __fdividef(x, 1.f + __expf(-x));   // silu
            }
            float4* dst = (float4*)&smem.p2.hidT[t][0];
            dst[0] = make_float4(xv[0], xv[1], xv[2], xv[3]);
            dst[1] = make_float4(xv[4], xv[5], xv[6], xv[7]);
        }
        __syncthreads();

        // ---- layer 2 matvec via f32x2: thread = (o, tt-range of 32) ----
        {
            const int o  = t & 31;
            const int tg = t >> 5;
            unsigned long long a01 = 0ULL, a23 = 0ULL, a45 = 0ULL, a67 = 0ULL;
#pragma unroll 8
            for (int u = 0; u < 32; u++) {
                const int tt = tg*32 + u;
                const float w = __ldg(&Wp2[(size_t)tt*OUTD + o]);
                unsigned long long ww; PACK2(ww, w);
                const ulonglong2 hA = *(const ulonglong2*)&smem.p2.hidT[tt][0];
                const ulonglong2 hB = *(const ulonglong2*)&smem.p2.hidT[tt][4];
                FMA_F32X2(a01, hA.x, ww, a01);
                FMA_F32X2(a23, hA.y, ww, a23);
                FMA_F32X2(a45, hB.x, ww, a45);
                FMA_F32X2(a67, hB.y, ww, a67);
            }
            unsigned int l0,h0,l1,h1,l2,h2,l3,h3;
            UNPACK2(l0, h0, a01); UNPACK2(l1, h1, a23);
            UNPACK2(l2, h2, a45); UNPACK2(l3, h3, a67);
            smem.p2.sp[tg*256 + 0*32 + o] = __uint_as_float(l0);
            smem.p2.sp[tg*256 + 1*32 + o] = __uint_as_float(h0);
            smem.p2.sp[tg*256 + 2*32 + o] = __uint_as_float(l1);
            smem.p2.sp[tg*256 + 3*32 + o] = __uint_as_float(h1);
            smem.p2.sp[tg*256 + 4*32 + o] = __uint_as_float(l2);
            smem.p2.sp[tg*256 + 5*32 + o] = __uint_as_float(h2);
            smem.p2.sp[tg*256 + 6*32 + o] = __uint_as_float(l3);
            smem.p2.sp[tg*256 + 7*32 + o] = __uint_as_float(h3);
        }
        __syncthreads();

        // ---- finalize: combine 8 partials, bias + direction, store ----
        {
            const int k = t >> 5;
            const int o = t & 31;
            float acc = bp2[o];
#pragma unroll
            for (int tg = 0; tg < 8; tg++) acc += smem.p2.sp[tg*256 + t];
            const size_t ob = ((size_t)(row*KK + k)*OUTD + o) * 3;
            cout[ob+0] = acc * smem.p2.sdx[k];
            cout[ob+1] = acc * smem.p2.sdy[k];
            cout[ob+2] = acc * smem.p2.sdz[k];
        }
    }
}

// ---------------------------------------------------------------------------
extern "C" void kernel_launch(void* const* d_in, const int* in_sizes, int n_in,
                              void* d_out, int out_size) {
    const int*   z   = (const int*)  d_in[0];
    const float* r   = (const float*)d_in[1];
    const float* h   = (const float*)d_in[2];
    const float* Wa  = (const float*)d_in[3];
    const float* ba  = (const float*)d_in[4];
    const float* Wp1 = (const float*)d_in[5];
    const float* bp1 = (const float*)d_in[6];
    const float* Wp2 = (const float*)d_in[7];
    const float* bp2 = (const float*)d_in[8];

    float* out = (float*)d_out;
    const int CSZ  = Nn*MA*KK*OUTD*3;         // 786432
    const int PREF = ROWS + ROWS*3;           // 4096 (z + r)
    const int has_prefix = (out_size == CSZ + PREF) ? 1 : 0;
    float* cout = has_prefix ? (out + PREF) : out;

    int dev = 0;
    cudaGetDevice(&dev);
    int sms = 148;
    cudaDeviceGetAttribute(&sms, cudaDevAttrMultiProcessorCount, dev);
    int blocks = sms * 7;                      // all co-resident (LB(256,7))
    if (blocks > ROWS) blocks = ROWS;          // 1024 rows max useful
    if (blocks < 512)  blocks = 512;           // phase-1 needs 512 blocks

    kFused<<<blocks, 256>>>(z, r, h, Wa, ba, Wp1, bp1, Wp2, bp2,
                            out, has_prefix, cout, blocks);
}